// round 1
// baseline (speedup 1.0000x reference)
#include <cuda_runtime.h>
#include <math.h>

#define H     1024
#define H4    (H/4)
#define VOUT  32000
#define ML    128
#define ATT   129   // ML + 1

// ---------------- device scratch (no allocation allowed) ----------------
__device__ float g_hbuf[2][H];          // hidden state ping-pong (encoder then decoder)
__device__ float g_enc_out[ATT * H];    // encoder outputs, row ML stays zero
__device__ float g_emb[H];              // decoder input embedding for current step
__device__ float g_attn[ATT];           // attention logits for current step
__device__ float g_ctx[H];              // attention context
__device__ float g_comb[H];             // relu(comb_W @ [emb;ctx] + b)
__device__ float g_logits[VOUT];        // vocab logits
__device__ unsigned long long g_maxpack;// packed (sortable-float, ~index) running max
__device__ float g_sumexp;              // sum of exp(logit - max)

// ---------------- helpers ----------------
__device__ __forceinline__ float wredsum(float v) {
#pragma unroll
    for (int o = 16; o > 0; o >>= 1) v += __shfl_xor_sync(0xffffffffu, v, o);
    return v;
}

__device__ __forceinline__ unsigned long long packf(float v, int idx) {
    unsigned u = __float_as_uint(v);
    u = (u & 0x80000000u) ? ~u : (u | 0x80000000u);   // total order on floats
    // invert index so ties resolve to LOWEST index (jnp.argmax semantics)
    return ((unsigned long long)u << 32) | (unsigned)(~(unsigned)idx);
}

__device__ __forceinline__ float unpack_max(unsigned long long p) {
    unsigned u = (unsigned)(p >> 32);
    unsigned b = (u & 0x80000000u) ? (u & 0x7fffffffu) : ~u;
    return __uint_as_float(b);
}

__device__ __forceinline__ int unpack_idx(unsigned long long p) {
    return (int)(~(unsigned)(p & 0xffffffffu));
}

__device__ __forceinline__ float dot4(float4 a, float4 b) {
    return a.x * b.x + a.y * b.y + a.z * b.z + a.w * b.w;
}

// ---------------- kernels ----------------

// zero h0 and the padding row of encoder_outputs
__global__ void k_init() {
    int i = blockIdx.x * blockDim.x + threadIdx.x;
    if (i < H) {
        g_hbuf[0][i] = 0.f;
        g_enc_out[ML * H + i] = 0.f;
    }
}

// One GRU step. Warp j computes the 6 dot products for element j, then the
// full gate math -> no intra-step synchronization needed.
// If emb_table != null: x = emb_table[tokens[t]]. Else x = g_comb (decoder).
__global__ void __launch_bounds__(256) k_gru(
    const float* __restrict__ Wih, const float* __restrict__ Whh,
    const float* __restrict__ bih, const float* __restrict__ bhh,
    const float* __restrict__ emb_table, const int* __restrict__ tokens,
    int t, int hsel, int write_enc)
{
    if (blockIdx.x == 0 && threadIdx.x == 0) {   // reset reduction state for this step
        g_maxpack = 0ull;
        g_sumexp  = 0.f;
    }
    const float* x = emb_table ? (emb_table + (size_t)tokens[t] * H) : g_comb;
    const float* h = g_hbuf[hsel];
    float*      ho = g_hbuf[hsel ^ 1];

    int wid  = (blockIdx.x * blockDim.x + threadIdx.x) >> 5;   // 0..1023
    int lane = threadIdx.x & 31;
    if (wid >= H) return;

    const float4* x4 = (const float4*)x;
    const float4* h4 = (const float4*)h;
    const float4* Wir = (const float4*)(Wih + (size_t)wid * H);
    const float4* Wiz = (const float4*)(Wih + (size_t)(wid + H) * H);
    const float4* Win = (const float4*)(Wih + (size_t)(wid + 2 * H) * H);
    const float4* Whr = (const float4*)(Whh + (size_t)wid * H);
    const float4* Whz = (const float4*)(Whh + (size_t)(wid + H) * H);
    const float4* Whn = (const float4*)(Whh + (size_t)(wid + 2 * H) * H);

    float ir = 0.f, iz = 0.f, inn = 0.f, hr = 0.f, hz = 0.f, hn = 0.f;
#pragma unroll 4
    for (int k = lane; k < H4; k += 32) {
        float4 xv = x4[k], hv = h4[k];
        ir  += dot4(Wir[k], xv);
        iz  += dot4(Wiz[k], xv);
        inn += dot4(Win[k], xv);
        hr  += dot4(Whr[k], hv);
        hz  += dot4(Whz[k], hv);
        hn  += dot4(Whn[k], hv);
    }
    ir = wredsum(ir);  iz = wredsum(iz);  inn = wredsum(inn);
    hr = wredsum(hr);  hz = wredsum(hz);  hn  = wredsum(hn);

    if (lane == 0) {
        ir  += bih[wid];          hr += bhh[wid];
        iz  += bih[wid + H];      hz += bhh[wid + H];
        inn += bih[wid + 2 * H];  hn += bhh[wid + 2 * H];
        float r = 1.f / (1.f + expf(-(ir + hr)));
        float z = 1.f / (1.f + expf(-(iz + hz)));
        float n = tanhf(inn + r * hn);
        float hnew = (1.f - z) * n + z * h[wid];
        ho[wid] = hnew;
        if (write_enc) g_enc_out[(size_t)t * H + wid] = hnew;
    }
}

// one-time decoder prep for step 0: tok = SOS(0), h = g_hbuf[0]
__global__ void __launch_bounds__(256) k_prep0(
    const float* __restrict__ attn_W, const float* __restrict__ attn_b,
    const float* __restrict__ dec_emb)
{
    int gtid = blockIdx.x * blockDim.x + threadIdx.x;
    if (gtid < H) g_emb[gtid] = dec_emb[gtid];   // tok = 0

    int wid = gtid >> 5, lane = gtid & 31;
    if (wid < ATT) {
        const float4* W  = (const float4*)(attn_W + (size_t)wid * 2 * H);
        const float4* e4 = (const float4*)dec_emb;       // row 0
        const float4* h4 = (const float4*)g_hbuf[0];
        float a = 0.f;
#pragma unroll 4
        for (int k = lane; k < H4; k += 32) a += dot4(W[k], e4[k]);
#pragma unroll 4
        for (int k = lane; k < H4; k += 32) a += dot4(W[k + H4], h4[k]);
        a = wredsum(a);
        if (lane == 0) g_attn[wid] = a + attn_b[wid];
    }
}

// softmax over 129 attn logits (redundant per CTA) + context vector
__global__ void __launch_bounds__(256) k_ctx() {
    __shared__ float sa[ATT];
    __shared__ float sw[ATT];
    __shared__ float red[256];
    int tid = threadIdx.x;

    for (int t = tid; t < ATT; t += 256) sa[t] = g_attn[t];
    __syncthreads();

    float lm = -1e30f;
    for (int t = tid; t < ATT; t += 256) lm = fmaxf(lm, sa[t]);
    red[tid] = lm; __syncthreads();
#pragma unroll
    for (int s = 128; s > 0; s >>= 1) {
        if (tid < s) red[tid] = fmaxf(red[tid], red[tid + s]);
        __syncthreads();
    }
    float mx = red[0]; __syncthreads();

    float ls = 0.f;
    for (int t = tid; t < ATT; t += 256) {
        float e = expf(sa[t] - mx);
        sw[t] = e;
        ls += e;
    }
    red[tid] = ls; __syncthreads();
#pragma unroll
    for (int s = 128; s > 0; s >>= 1) {
        if (tid < s) red[tid] += red[tid + s];
        __syncthreads();
    }
    float S = red[0]; __syncthreads();

    int j = blockIdx.x * 256 + tid;          // 4 CTAs x 256 = 1024
    float acc = 0.f;
#pragma unroll 4
    for (int t = 0; t < ATT; t++) acc += sw[t] * g_enc_out[(size_t)t * H + j];
    g_ctx[j] = acc / S;
}

// comb = relu(comb_W @ [emb; ctx] + comb_b), warp per output element
__global__ void __launch_bounds__(256) k_comb(
    const float* __restrict__ comb_W, const float* __restrict__ comb_b)
{
    int wid = (blockIdx.x * 256 + threadIdx.x) >> 5;
    int lane = threadIdx.x & 31;
    const float4* W  = (const float4*)(comb_W + (size_t)wid * 2 * H);
    const float4* e4 = (const float4*)g_emb;
    const float4* c4 = (const float4*)g_ctx;
    float a = 0.f;
#pragma unroll 4
    for (int k = lane; k < H4; k += 32) a += dot4(W[k], e4[k]);
#pragma unroll 4
    for (int k = lane; k < H4; k += 32) a += dot4(W[k + H4], c4[k]);
    a = wredsum(a);
    if (lane == 0) {
        a += comb_b[wid];
        g_comb[wid] = a > 0.f ? a : 0.f;
    }
}

// logits = out_W @ h + out_b ; track (max, argmax) with one atomic per CTA
__global__ void __launch_bounds__(256) k_logits(
    const float* __restrict__ out_W, const float* __restrict__ out_b, int hsel)
{
    __shared__ unsigned long long sbest[8];
    int lane = threadIdx.x & 31;
    int warp = threadIdx.x >> 5;
    int wid0 = (blockIdx.x * 256 + threadIdx.x) >> 5;
    int nw   = gridDim.x * 8;

    const float4* h4 = (const float4*)g_hbuf[hsel];
    float4 hv[8];
#pragma unroll
    for (int i = 0; i < 8; i++) hv[i] = h4[lane + 32 * i];   // h cached in registers

    unsigned long long best = 0ull;
    for (int row = wid0; row < VOUT; row += nw) {
        const float4* W = (const float4*)(out_W + (size_t)row * H);
        float a = 0.f;
#pragma unroll
        for (int i = 0; i < 8; i++) a += dot4(W[lane + 32 * i], hv[i]);
        a = wredsum(a);
        if (lane == 0) {
            a += out_b[row];
            g_logits[row] = a;
            unsigned long long p = packf(a, row);
            if (p > best) best = p;
        }
    }
    if (lane == 0) sbest[warp] = best;
    __syncthreads();
    if (threadIdx.x == 0) {
        unsigned long long b = sbest[0];
#pragma unroll
        for (int i = 1; i < 8; i++) if (sbest[i] > b) b = sbest[i];
        atomicMax(&g_maxpack, b);
    }
}

// sum of exp(logit - max), one atomicAdd per CTA
__global__ void __launch_bounds__(256) k_lse() {
    __shared__ float sm[8];
    float mx = unpack_max(g_maxpack);
    float s = 0.f;
    for (int v = blockIdx.x * 256 + threadIdx.x; v < VOUT; v += gridDim.x * 256)
        s += expf(g_logits[v] - mx);
    s = wredsum(s);
    int lane = threadIdx.x & 31, warp = threadIdx.x >> 5;
    if (lane == 0) sm[warp] = s;
    __syncthreads();
    if (threadIdx.x == 0) {
        float t = 0.f;
#pragma unroll
        for (int i = 0; i < 8; i++) t += sm[i];
        atomicAdd(&g_sumexp, t);
    }
}

// write logp row; fuse next step's prep (emb copy + attention logits)
__global__ void __launch_bounds__(256) k_out(
    float* __restrict__ out, int s,
    const float* __restrict__ attn_W, const float* __restrict__ attn_b,
    const float* __restrict__ dec_emb, int hsel)
{
    unsigned long long mp = g_maxpack;
    float mx = unpack_max(mp);
    int tok  = unpack_idx(mp);
    float lse = mx + logf(g_sumexp);

    int gtid = blockIdx.x * 256 + threadIdx.x;
    for (int v = gtid; v < VOUT; v += gridDim.x * 256)
        out[(size_t)s * VOUT + v] = g_logits[v] - lse;

    // ---- prep for next step (harmless extra work on the last step) ----
    if (gtid < H) g_emb[gtid] = dec_emb[(size_t)tok * H + gtid];

    int wid = gtid >> 5, lane = gtid & 31;
    if (wid < ATT) {
        const float4* W  = (const float4*)(attn_W + (size_t)wid * 2 * H);
        const float4* e4 = (const float4*)(dec_emb + (size_t)tok * H);
        const float4* h4 = (const float4*)g_hbuf[hsel];
        float a = 0.f;
#pragma unroll 4
        for (int k = lane; k < H4; k += 32) a += dot4(W[k], e4[k]);
#pragma unroll 4
        for (int k = lane; k < H4; k += 32) a += dot4(W[k + H4], h4[k]);
        a = wredsum(a);
        if (lane == 0) g_attn[wid] = a + attn_b[wid];
    }
}

// ---------------- host launcher (graph-capturable) ----------------
extern "C" void kernel_launch(void* const* d_in, const int* in_sizes, int n_in,
                              void* d_out, int out_size)
{
    const int*   tokens  = (const int*)  d_in[0];
    // d_in[1] = max_length (compile-time ML=128)
    const float* enc_emb = (const float*)d_in[2];
    const float* enc_Wih = (const float*)d_in[3];
    const float* enc_Whh = (const float*)d_in[4];
    const float* enc_bih = (const float*)d_in[5];
    const float* enc_bhh = (const float*)d_in[6];
    const float* dec_emb = (const float*)d_in[7];
    const float* attn_W  = (const float*)d_in[8];
    const float* attn_b  = (const float*)d_in[9];
    const float* comb_W  = (const float*)d_in[10];
    const float* comb_b  = (const float*)d_in[11];
    const float* dec_Wih = (const float*)d_in[12];
    const float* dec_Whh = (const float*)d_in[13];
    const float* dec_bih = (const float*)d_in[14];
    const float* dec_bhh = (const float*)d_in[15];
    const float* out_W   = (const float*)d_in[16];
    const float* out_b   = (const float*)d_in[17];
    float* out = (float*)d_out;

    k_init<<<4, 256>>>();

    // encoder: 128 sequential GRU steps
    for (int t = 0; t < ML; t++)
        k_gru<<<128, 256>>>(enc_Wih, enc_Whh, enc_bih, enc_bhh,
                            enc_emb, tokens, t, t & 1, 1);
    // after t=127 the hidden state sits in g_hbuf[0]

    k_prep0<<<17, 256>>>(attn_W, attn_b, dec_emb);

    // decoder: 128 sequential steps
    for (int s = 0; s < ML; s++) {
        int hc = s & 1;        // current h
        int hn = hc ^ 1;       // new h
        k_ctx   <<<4,   256>>>();
        k_comb  <<<128, 256>>>(comb_W, comb_b);
        k_gru   <<<128, 256>>>(dec_Wih, dec_Whh, dec_bih, dec_bhh,
                               nullptr, nullptr, 0, hc, 0);
        k_logits<<<250, 256>>>(out_W, out_b, hn);
        k_lse   <<<64,  256>>>();
        k_out   <<<68,  256>>>(out, s, attn_W, attn_b, dec_emb, hn);
    }
}

// round 2
// speedup vs baseline: 1.7325x; 1.7325x over previous
#include <cuda_runtime.h>
#include <math.h>

#define H      1024
#define H4     256          // H/4
#define VOUT   32000
#define ML     128
#define ATT    129          // ML + 1
#define GRID   148
#define BLOCK  512
#define WPB    (BLOCK/32)   // 16 warps per block
#define NWARPS (GRID*WPB)   // 2368
#define MAXSLOT 14          // ceil(VOUT/NWARPS)

// ---------------- device scratch (static, no allocation) ----------------
__device__ float g_h[2][H];
__device__ float g_enc_out[ATT * H];
__device__ float g_attn[ATT];
__device__ float g_ctx[H];
__device__ float g_comb[H];
__device__ float g_logits[VOUT];
__device__ unsigned long long g_pmax[GRID];  // per-CTA packed (max,argmax)
__device__ float g_psum[GRID];               // per-CTA sumexp wrt its own max
__device__ int g_tok;

__device__ unsigned g_bar_count = 0;
__device__ unsigned g_bar_gen   = 0;

// ---------------- helpers ----------------
__device__ __forceinline__ float wredsum(float v) {
#pragma unroll
    for (int o = 16; o > 0; o >>= 1) v += __shfl_xor_sync(0xffffffffu, v, o);
    return v;
}

__device__ __forceinline__ unsigned long long packf(float v, int idx) {
    unsigned u = __float_as_uint(v);
    u = (u & 0x80000000u) ? ~u : (u | 0x80000000u);   // totally ordered float bits
    return ((unsigned long long)u << 32) | (unsigned)(~(unsigned)idx); // tie -> lowest idx
}
__device__ __forceinline__ float unpack_max(unsigned long long p) {
    unsigned u = (unsigned)(p >> 32);
    unsigned b = (u & 0x80000000u) ? (u & 0x7fffffffu) : ~u;
    return __uint_as_float(b);
}
__device__ __forceinline__ int unpack_idx(unsigned long long p) {
    return (int)(~(unsigned)(p & 0xffffffffu));
}

__device__ __forceinline__ float dot4(float4 a, float4 b) {
    return a.x * b.x + a.y * b.y + a.z * b.z + a.w * b.w;
}

// ---------------- grid-wide barrier (CG grid.sync pattern) ----------------
__device__ __forceinline__ unsigned ld_acq(unsigned* p) {
    unsigned v;
    asm volatile("ld.acquire.gpu.u32 %0, [%1];" : "=r"(v) : "l"(p) : "memory");
    return v;
}
__device__ __forceinline__ void st_rel(unsigned* p, unsigned v) {
    asm volatile("st.release.gpu.u32 [%0], %1;" :: "l"(p), "r"(v) : "memory");
}

__device__ __forceinline__ void gsync() {
    __syncthreads();
    if (threadIdx.x == 0) {
        unsigned gen = ld_acq(&g_bar_gen);        // read BEFORE arriving
        __threadfence();                          // publish this CTA's writes
        if (atomicAdd(&g_bar_count, 1) == GRID - 1) {
            g_bar_count = 0;
            st_rel(&g_bar_gen, gen + 1);          // release: reset visible first
        } else {
            while (ld_acq(&g_bar_gen) == gen) { } // acquire spin
        }
    }
    __syncthreads();
}

// ---------------- phases ----------------

// GRU step: rows spread across ALL CTAs: row = wib*GRID + cta (wib<7)
__device__ __forceinline__ void gru_phase(
    const float* __restrict__ Wih, const float* __restrict__ Whh,
    const float* __restrict__ bih, const float* __restrict__ bhh,
    const float* __restrict__ x, const float* __restrict__ h,
    float* __restrict__ ho, float* __restrict__ enc_row)
{
    int wib = threadIdx.x >> 5;
    int lane = threadIdx.x & 31;
    if (wib >= 7) return;
    int row = wib * GRID + (int)blockIdx.x;
    if (row >= H) return;

    const float4* x4 = (const float4*)x;
    const float4* h4 = (const float4*)h;
    const float4* Wir = (const float4*)(Wih + (size_t)row * H);
    const float4* Wiz = (const float4*)(Wih + (size_t)(row + H) * H);
    const float4* Win = (const float4*)(Wih + (size_t)(row + 2 * H) * H);
    const float4* Whr = (const float4*)(Whh + (size_t)row * H);
    const float4* Whz = (const float4*)(Whh + (size_t)(row + H) * H);
    const float4* Whn = (const float4*)(Whh + (size_t)(row + 2 * H) * H);

    float ir = 0.f, iz = 0.f, inn = 0.f, hr = 0.f, hz = 0.f, hn = 0.f;
#pragma unroll 4
    for (int k = lane; k < H4; k += 32) {
        float4 xv = x4[k], hv = h4[k];
        ir  += dot4(Wir[k], xv);
        iz  += dot4(Wiz[k], xv);
        inn += dot4(Win[k], xv);
        hr  += dot4(Whr[k], hv);
        hz  += dot4(Whz[k], hv);
        hn  += dot4(Whn[k], hv);
    }
    ir = wredsum(ir);  iz = wredsum(iz);  inn = wredsum(inn);
    hr = wredsum(hr);  hz = wredsum(hz);  hn  = wredsum(hn);

    if (lane == 0) {
        ir  += bih[row];          hr += bhh[row];
        iz  += bih[row + H];      hz += bhh[row + H];
        inn += bih[row + 2 * H];  hn += bhh[row + 2 * H];
        float r = 1.f / (1.f + expf(-(ir + hr)));
        float z = 1.f / (1.f + expf(-(iz + hz)));
        float n = tanhf(inn + r * hn);
        float hnew = (1.f - z) * n + z * h[row];
        ho[row] = hnew;
        if (enc_row) enc_row[row] = hnew;
    }
}

// attention softmax + context. CTAs 0..31 each produce 32 ctx elems (coalesced).
__device__ __forceinline__ void ctx_phase(float* s_e, float* s_red)
{
    if ((int)blockIdx.x >= 32) return;   // uniform per block
    int tid = threadIdx.x;
    float v = (tid < ATT) ? g_attn[tid] : -INFINITY;
    s_red[tid] = v; __syncthreads();
#pragma unroll
    for (int s = BLOCK / 2; s > 0; s >>= 1) {
        if (tid < s) s_red[tid] = fmaxf(s_red[tid], s_red[tid + s]);
        __syncthreads();
    }
    float mx = s_red[0]; __syncthreads();
    float e = (tid < ATT) ? expf(v - mx) : 0.f;
    if (tid < ATT) s_e[tid] = e;
    s_red[tid] = e; __syncthreads();
#pragma unroll
    for (int s = BLOCK / 2; s > 0; s >>= 1) {
        if (tid < s) s_red[tid] += s_red[tid + s];
        __syncthreads();
    }
    float invS = 1.f / s_red[0];
    __syncthreads();
    if ((tid >> 5) == 0) {
        int lane = tid & 31;
        int j = (int)blockIdx.x * 32 + lane;
        float acc = 0.f;
#pragma unroll 4
        for (int t = 0; t < ATT; t++) acc += s_e[t] * g_enc_out[t * H + j];
        g_ctx[j] = acc * invS;
    }
}

// comb = relu(comb_W @ [emb; ctx] + b)
__device__ __forceinline__ void comb_phase(
    const float* __restrict__ comb_W, const float* __restrict__ comb_b,
    const float* __restrict__ dec_emb)
{
    int wib = threadIdx.x >> 5;
    int lane = threadIdx.x & 31;
    if (wib >= 7) return;
    int row = wib * GRID + (int)blockIdx.x;
    if (row >= H) return;
    int tok = g_tok;
    const float4* W  = (const float4*)(comb_W + (size_t)row * 2 * H);
    const float4* e4 = (const float4*)(dec_emb + (size_t)tok * H);
    const float4* c4 = (const float4*)g_ctx;
    float a = 0.f;
#pragma unroll 4
    for (int k = lane; k < H4; k += 32) a += dot4(W[k], e4[k]);
#pragma unroll 4
    for (int k = lane; k < H4; k += 32) a += dot4(W[k + H4], c4[k]);
    a = wredsum(a);
    if (lane == 0) {
        a += comb_b[row];
        g_comb[row] = fmaxf(a, 0.f);
    }
}

// logits GEMV + per-CTA (packed max, local sumexp) partials
__device__ __forceinline__ void logits_phase(
    const float* __restrict__ out_W, const float* __restrict__ out_b,
    const float* __restrict__ h,
    float* s_slot, unsigned long long* s_best, float* s_red)
{
    int tid = threadIdx.x, lane = tid & 31, wib = tid >> 5;
    int gw = (int)blockIdx.x * WPB + wib;

    if (tid < WPB * MAXSLOT) s_slot[tid] = -INFINITY;
    __syncthreads();

    const float4* h4 = (const float4*)h;
    float4 hv[8];
#pragma unroll
    for (int i = 0; i < 8; i++) hv[i] = h4[lane + 32 * i];

    unsigned long long best = 0ull;
    int ns = 0;
    for (int row = gw; row < VOUT; row += NWARPS, ns++) {
        const float4* W = (const float4*)(out_W + (size_t)row * H);
        float a = 0.f;
#pragma unroll
        for (int i = 0; i < 8; i++) a += dot4(__ldcs(&W[lane + 32 * i]), hv[i]);
        a = wredsum(a);
        if (lane == 0) {
            a += out_b[row];
            g_logits[row] = a;
            s_slot[wib * MAXSLOT + ns] = a;
            unsigned long long p = packf(a, row);
            if (p > best) best = p;
        }
    }
    if (lane == 0) s_best[wib] = best;
    __syncthreads();
    if (tid == 0) {
        unsigned long long b = s_best[0];
#pragma unroll
        for (int i = 1; i < WPB; i++) if (s_best[i] > b) b = s_best[i];
        s_best[0] = b;
    }
    __syncthreads();
    unsigned long long cb = s_best[0];
    float m = unpack_max(cb);
    float e = (tid < WPB * MAXSLOT) ? expf(s_slot[tid] - m) : 0.f;  // -inf slots -> 0
    s_red[tid] = e; __syncthreads();
#pragma unroll
    for (int s = BLOCK / 2; s > 0; s >>= 1) {
        if (tid < s) s_red[tid] += s_red[tid + s];
        __syncthreads();
    }
    if (tid == 0) {
        g_pmax[blockIdx.x] = cb;
        g_psum[blockIdx.x] = s_red[0];
    }
}

// combine partials (redundant per CTA, deterministic), write logp row,
// and fuse next-step attention-logit prep
__device__ __forceinline__ void out_phase(
    float* __restrict__ out, int step,
    const float* __restrict__ attn_W, const float* __restrict__ attn_b,
    const float* __restrict__ dec_emb, const float* __restrict__ h,
    float* s_red, unsigned long long* s_pred)
{
    int tid = threadIdx.x, lane = tid & 31, wib = tid >> 5;
    unsigned long long p = (tid < GRID) ? g_pmax[tid] : 0ull;
    s_pred[tid] = p; __syncthreads();
#pragma unroll
    for (int s = BLOCK / 2; s > 0; s >>= 1) {
        if (tid < s && s_pred[tid + s] > s_pred[tid]) s_pred[tid] = s_pred[tid + s];
        __syncthreads();
    }
    unsigned long long gp = s_pred[0];
    __syncthreads();
    float M  = unpack_max(gp);
    int tok  = unpack_idx(gp);

    float term = (tid < GRID) ? g_psum[tid] * expf(unpack_max(p) - M) : 0.f;
    s_red[tid] = term; __syncthreads();
#pragma unroll
    for (int s = BLOCK / 2; s > 0; s >>= 1) {
        if (tid < s) s_red[tid] += s_red[tid + s];
        __syncthreads();
    }
    float lse = M + logf(s_red[0]);
    __syncthreads();

    int g = (int)blockIdx.x * BLOCK + tid;
    if (g < VOUT) out[(size_t)step * VOUT + g] = g_logits[g] - lse;

    // next-step attention logits: warp 0 of CTA c (c < 129) does row c
    if ((int)blockIdx.x < ATT && wib == 0) {
        const float4* W  = (const float4*)(attn_W + (size_t)blockIdx.x * 2 * H);
        const float4* e4 = (const float4*)(dec_emb + (size_t)tok * H);
        const float4* h4 = (const float4*)h;
        float a = 0.f;
#pragma unroll 4
        for (int k = lane; k < H4; k += 32) a += dot4(W[k], e4[k]);
#pragma unroll 4
        for (int k = lane; k < H4; k += 32) a += dot4(W[k + H4], h4[k]);
        a = wredsum(a);
        if (lane == 0) g_attn[blockIdx.x] = a + attn_b[blockIdx.x];
    }
    if (blockIdx.x == 0 && tid == 0) g_tok = tok;
}

// ---------------- the single persistent kernel ----------------
__global__ void __launch_bounds__(BLOCK, 1) k_all(
    const int* __restrict__ tokens,
    const float* __restrict__ enc_emb,
    const float* __restrict__ enc_Wih, const float* __restrict__ enc_Whh,
    const float* __restrict__ enc_bih, const float* __restrict__ enc_bhh,
    const float* __restrict__ dec_emb,
    const float* __restrict__ attn_W, const float* __restrict__ attn_b,
    const float* __restrict__ comb_W, const float* __restrict__ comb_b,
    const float* __restrict__ dec_Wih, const float* __restrict__ dec_Whh,
    const float* __restrict__ dec_bih, const float* __restrict__ dec_bhh,
    const float* __restrict__ out_W, const float* __restrict__ out_b,
    float* __restrict__ out)
{
    __shared__ float s_red[BLOCK];
    __shared__ unsigned long long s_pred[BLOCK];
    __shared__ float s_slot[WPB * MAXSLOT];     // also reused as softmax e[] (ATT<=224)
    __shared__ unsigned long long s_best[WPB];

    int tid = threadIdx.x;

    // init: h0 = 0, padding row of enc_out = 0
    {
        int g = (int)blockIdx.x * BLOCK + tid;
        if (g < H) { g_h[0][g] = 0.f; g_enc_out[ML * H + g] = 0.f; }
    }
    gsync();

    // ---- encoder ----
    for (int t = 0; t < ML; t++) {
        const float* x = enc_emb + (size_t)tokens[t] * H;
        gru_phase(enc_Wih, enc_Whh, enc_bih, enc_bhh, x,
                  g_h[t & 1], g_h[(t & 1) ^ 1], g_enc_out + (size_t)t * H);
        gsync();
    }
    // final encoder hidden now in g_h[0]

    // ---- decoder prep (tok = SOS = 0) ----
    if ((int)blockIdx.x < ATT && (tid >> 5) == 0) {
        int lane = tid & 31;
        const float4* W  = (const float4*)(attn_W + (size_t)blockIdx.x * 2 * H);
        const float4* e4 = (const float4*)dec_emb;     // row 0
        const float4* h4 = (const float4*)g_h[0];
        float a = 0.f;
#pragma unroll 4
        for (int k = lane; k < H4; k += 32) a += dot4(W[k], e4[k]);
#pragma unroll 4
        for (int k = lane; k < H4; k += 32) a += dot4(W[k + H4], h4[k]);
        a = wredsum(a);
        if (lane == 0) g_attn[blockIdx.x] = a + attn_b[blockIdx.x];
    }
    if (blockIdx.x == 0 && tid == 0) g_tok = 0;
    gsync();

    // ---- decoder ----
    for (int s = 0; s < ML; s++) {
        const float* hc = g_h[s & 1];
        float* hn = g_h[(s & 1) ^ 1];

        ctx_phase(s_slot, s_red);                              gsync();
        comb_phase(comb_W, comb_b, dec_emb);                   gsync();
        gru_phase(dec_Wih, dec_Whh, dec_bih, dec_bhh,
                  g_comb, hc, hn, nullptr);                    gsync();
        logits_phase(out_W, out_b, hn, s_slot, s_best, s_red); gsync();
        out_phase(out, s, attn_W, attn_b, dec_emb, hn,
                  s_red, s_pred);                              gsync();
    }
}

// ---------------- host launcher ----------------
extern "C" void kernel_launch(void* const* d_in, const int* in_sizes, int n_in,
                              void* d_out, int out_size)
{
    const int*   tokens  = (const int*)  d_in[0];
    // d_in[1] = max_length (compile-time ML=128)
    const float* enc_emb = (const float*)d_in[2];
    const float* enc_Wih = (const float*)d_in[3];
    const float* enc_Whh = (const float*)d_in[4];
    const float* enc_bih = (const float*)d_in[5];
    const float* enc_bhh = (const float*)d_in[6];
    const float* dec_emb = (const float*)d_in[7];
    const float* attn_W  = (const float*)d_in[8];
    const float* attn_b  = (const float*)d_in[9];
    const float* comb_W  = (const float*)d_in[10];
    const float* comb_b  = (const float*)d_in[11];
    const float* dec_Wih = (const float*)d_in[12];
    const float* dec_Whh = (const float*)d_in[13];
    const float* dec_bih = (const float*)d_in[14];
    const float* dec_bhh = (const float*)d_in[15];
    const float* out_W   = (const float*)d_in[16];
    const float* out_b   = (const float*)d_in[17];
    float* out = (float*)d_out;

    k_all<<<GRID, BLOCK>>>(tokens, enc_emb, enc_Wih, enc_Whh, enc_bih, enc_bhh,
                           dec_emb, attn_W, attn_b, comb_W, comb_b,
                           dec_Wih, dec_Whh, dec_bih, dec_bhh,
                           out_W, out_b, out);
}